// round 9
// baseline (speedup 1.0000x reference)
#include <cuda_runtime.h>
#include <cuda_bf16.h>
#include <cstdint>

// Problem constants (shape fixed by dataset: img [64, 3, 512, 512])
constexpr int NCH = 192;           // 64*3 channels
constexpr int P   = 262144;        // 512*512 pixels / channel
constexpr int NB  = 256;           // bins

// Pipeline structure (identical topology to the 93.8us R7 kernel)
constexpr int GROUPS = 8;
constexpr int CPG    = NCH / GROUPS;   // 24 channels per group
constexpr int HPC    = 8;              // hist blocks per channel
constexpr int APC    = 16;             // apply blocks per channel
constexpr int NHIST  = CPG * HPC;      // 192
constexpr int NAPPLY = CPG * APC;      // 384
constexpr int NBLK   = NHIST + NAPPLY; // 576 <= 148*4 -> fully co-resident

// Scratch — __device__ globals. Zero at load; the kernel restores all of it
// to zero each run, so graph replays start clean with no cleanup launch.
__device__ int   g_hist [NCH * NB];
__device__ float g_lut  [NCH * NB];
__device__ int   g_cdone[NCH];       // hist blocks done per channel
__device__ int   g_ctr  [GROUPS];    // hist blocks done per group (release)
__device__ int   g_adone[GROUPS];    // apply blocks past spin per group

// ---------------------------------------------------------------------------
// Fused persistent kernel, role-specialized per block.
//  hist blocks (read-bound):  per-warp smem hists -> global; the LAST hist
//    block of a channel also computes that channel's LUT (exact PIL math),
//    zeroes g_hist[c], then bumps the group counter.
//  apply blocks (write-bound): spin on the group counter, load the ready
//    LUT, translate + __stcs-write their slice.
// Read and write DRAM streams overlap for the whole kernel.
// ---------------------------------------------------------------------------
__global__ void __launch_bounds__(256, 4) fused_kernel(const float* __restrict__ in,
                                                       float* __restrict__ out) {
    __shared__ int sh[8 * NB];     // hist: 8 warp-hists, then LUT build. apply: LUT.
    const int tid = threadIdx.x;
    const int bid = blockIdx.x;

    if (bid < NHIST) {
        // ---------------- HIST ROLE ----------------
        const int cg = bid / HPC;          // channel within group
        const int h  = bid % HPC;          // slice within channel
        int* const myh = &sh[(tid >> 5) * NB];
        __shared__ int s_ticket;

        for (int g = 0; g < GROUPS; g++) {
            const int c = g * CPG + cg;
            for (int i = tid; i < 8 * NB; i += 256) sh[i] = 0;
            __syncthreads();

            // 8192 float4 per slice, 2 loads in flight (R7 shape).
            const float4* bi =
                reinterpret_cast<const float4*>(in + (size_t)c * P) + h * (P / 4 / HPC);
            for (int i = tid; i < P / 4 / HPC; i += 512) {
                float4 a = bi[i];
                float4 b = bi[i + 256];
                atomicAdd(&myh[(int)a.x], 1);
                atomicAdd(&myh[(int)a.y], 1);
                atomicAdd(&myh[(int)a.z], 1);
                atomicAdd(&myh[(int)a.w], 1);
                atomicAdd(&myh[(int)b.x], 1);
                atomicAdd(&myh[(int)b.y], 1);
                atomicAdd(&myh[(int)b.z], 1);
                atomicAdd(&myh[(int)b.w], 1);
            }
            __syncthreads();

            int s = 0;
#pragma unroll
            for (int k = 0; k < 8; k++) s += sh[k * NB + tid];
            if (s) atomicAdd(&g_hist[c * NB + tid], s);
            __threadfence();               // publish hist before done-count
            __syncthreads();
            if (tid == 0) s_ticket = atomicAdd(&g_cdone[c], 1);
            __syncthreads();

            if (s_ticket == HPC - 1) {
                // -------- LUT producer for channel c --------
                __threadfence();           // acquire all hist contributions
                int* H  = sh;
                int* CS = sh + NB;
                int* RD = sh + 2 * NB;
                const int hv = __ldcg(&g_hist[c * NB + tid]);
                H[tid]  = hv;
                CS[tid] = hv;
                __syncthreads();
#pragma unroll
                for (int off = 1; off < NB; off <<= 1) {   // inclusive scan
                    int v = (tid >= off) ? CS[tid - off] : 0;
                    __syncthreads();
                    CS[tid] += v;
                    __syncthreads();
                }
                RD[tid] = hv ? tid : -1;                   // last nonzero bin
                __syncthreads();
#pragma unroll
                for (int sdx = 128; sdx > 0; sdx >>= 1) {
                    if (tid < sdx) RD[tid] = max(RD[tid], RD[tid + sdx]);
                    __syncthreads();
                }
                const int last_val = H[RD[0]];
                const int step = (P - last_val) / 255;     // exact PIL math
                const int safe = step > 0 ? step : 1;
                const int prev = tid ? CS[tid - 1] : 0;
                int lv = (prev + step / 2) / safe;
                lv = min(max(lv, 0), 255);
                if (step == 0) lv = tid;   // passthrough as identity LUT
                g_lut[c * NB + tid] = (float)lv;

                g_hist[c * NB + tid] = 0;  // restore for next graph replay
                if (tid == 0) g_cdone[c] = 0;
                __threadfence();           // LUT visible before group bump
            }
            // Every hist block bumps the group counter once; the channel's
            // producer bumps only after its LUT is published.
            __syncthreads();
            if (tid == 0) atomicAdd(&g_ctr[g], 1);
        }
    } else {
        // ---------------- APPLY ROLE ----------------
        const int a  = bid - NHIST;
        const int cg = a / APC;            // channel within group
        const int j  = a % APC;            // slice within channel
        float* LUT = reinterpret_cast<float*>(sh);
        __shared__ int s_ticket;

        for (int g = 0; g < GROUPS; g++) {
            const int c = g * CPG + cg;

            if (tid == 0) {
                while (*(volatile int*)&g_ctr[g] < NHIST) __nanosleep(128);
                s_ticket = atomicAdd(&g_adone[g], 1);
            }
            __syncthreads();
            __threadfence();
            LUT[tid] = __ldcg(&g_lut[c * NB + tid]);       // ready-made LUT
            __syncthreads();
            // Last apply block past the spin restores the group state.
            if (s_ticket == NAPPLY - 1 && tid == 0) {
                g_adone[g] = 0;
                g_ctr[g]   = 0;
            }

            // 4096 float4 per slice, 2 loads in flight (R7 shape),
            // evict-normal reads, streaming stores.
            const float4* bi =
                reinterpret_cast<const float4*>(in + (size_t)c * P) + j * (P / 4 / APC);
            float4* bo =
                reinterpret_cast<float4*>(out + (size_t)c * P) + j * (P / 4 / APC);
            for (int i = tid; i < P / 4 / APC; i += 512) {
                float4 x = bi[i];
                float4 y = bi[i + 256];
                float4 ox, oy;
                ox.x = LUT[(int)x.x]; ox.y = LUT[(int)x.y];
                ox.z = LUT[(int)x.z]; ox.w = LUT[(int)x.w];
                oy.x = LUT[(int)y.x]; oy.y = LUT[(int)y.y];
                oy.z = LUT[(int)y.z]; oy.w = LUT[(int)y.w];
                __stcs(&bo[i], ox);
                __stcs(&bo[i + 256], oy);
            }
            __syncthreads();               // smem (LUT) reuse next group
        }
    }
}

// ---------------------------------------------------------------------------
extern "C" void kernel_launch(void* const* d_in, const int* in_sizes, int n_in,
                              void* d_out, int out_size) {
    const float* img = (const float*)d_in[0];
    float* out = (float*)d_out;
    fused_kernel<<<NBLK, 256>>>(img, out);
}

// round 10
// speedup vs baseline: 1.1550x; 1.1550x over previous
#include <cuda_runtime.h>
#include <cuda_bf16.h>
#include <cstdint>

// Problem constants (shape fixed by dataset: img [64, 3, 512, 512])
constexpr int NCH = 192;           // 64*3 channels
constexpr int P   = 262144;        // 512*512 pixels / channel
constexpr int NB  = 256;           // bins

// Pipeline structure (identical topology to the 93.8us R7 kernel)
constexpr int GROUPS = 8;
constexpr int CPG    = NCH / GROUPS;   // 24 channels per group
constexpr int HPC    = 8;              // hist blocks per channel
constexpr int APC    = 16;             // apply blocks per channel
constexpr int NHIST  = CPG * HPC;      // 192
constexpr int NAPPLY = CPG * APC;      // 384
constexpr int NBLK   = NHIST + NAPPLY; // 576 <= 148*4 -> fully co-resident

// Scratch — __device__ globals. Zero at load; the kernel restores all of it
// to zero before exit, so graph replays start clean (no cleanup launch).
__device__ int g_hist [NCH * NB];
__device__ int g_ctr  [GROUPS];    // hist blocks done per group (release)
__device__ int g_adone[GROUPS];    // apply blocks past spin per group
__device__ int g_aread[NCH];       // apply blocks finished reading hist[c]

// ---------------------------------------------------------------------------
// Fused persistent kernel (R7 structure, verbatim):
//  - 192 hist blocks: stream input (read-bound), per-warp smem hists, publish
//    per channel, bump group counter.
//  - 384 apply blocks: spin on group counter, build LUT locally from g_hist
//    (redundant per block), translate + __stcs-write their slice.
// Added vs R7 (off critical path): last reader of each channel's hist zeroes
// it; last apply block per group resets group counters. Cleanup kernel gone.
// ---------------------------------------------------------------------------
__global__ void __launch_bounds__(256, 4) fused_kernel(const float* __restrict__ in,
                                                       float* __restrict__ out) {
    __shared__ int sh[8 * NB];     // hist: 8 per-warp hists. apply: H/CS/RED/LUT.
    const int tid = threadIdx.x;
    const int bid = blockIdx.x;

    if (bid < NHIST) {
        // ---------------- HIST ROLE (unchanged from R7) ----------------
        const int cg = bid / HPC;          // channel within group
        const int h  = bid % HPC;          // slice within channel
        int* const myh = &sh[(tid >> 5) * NB];

        for (int g = 0; g < GROUPS; g++) {
            const int c = g * CPG + cg;
            for (int i = tid; i < 8 * NB; i += 256) sh[i] = 0;
            __syncthreads();

            const float4* bi =
                reinterpret_cast<const float4*>(in + (size_t)c * P) + h * (P / 4 / HPC);
            for (int i = tid; i < P / 4 / HPC; i += 512) {   // 8192 float4 / slice
                float4 a = bi[i];
                float4 b = bi[i + 256];
                atomicAdd(&myh[(int)a.x], 1);
                atomicAdd(&myh[(int)a.y], 1);
                atomicAdd(&myh[(int)a.z], 1);
                atomicAdd(&myh[(int)a.w], 1);
                atomicAdd(&myh[(int)b.x], 1);
                atomicAdd(&myh[(int)b.y], 1);
                atomicAdd(&myh[(int)b.z], 1);
                atomicAdd(&myh[(int)b.w], 1);
            }
            __syncthreads();

            int s = 0;
#pragma unroll
            for (int k = 0; k < 8; k++) s += sh[k * NB + tid];
            if (s) atomicAdd(&g_hist[c * NB + tid], s);

            __threadfence();               // release my hist contributions
            __syncthreads();               // all threads' atomics+fences done
            if (tid == 0) atomicAdd(&g_ctr[g], 1);
        }
    } else {
        // ---------------- APPLY ROLE (R7 + in-kernel cleanup) ----------------
        const int a  = bid - NHIST;
        const int cg = a / APC;            // channel within group
        const int j  = a % APC;            // slice within channel
        int*   H   = sh;
        int*   CS  = sh + NB;
        int*   RED = sh + 2 * NB;
        float* LUT = reinterpret_cast<float*>(sh + 3 * NB);
        __shared__ int s_ticket;

        for (int g = 0; g < GROUPS; g++) {
            const int c = g * CPG + cg;

            // Wait until all hist blocks of this group have published.
            if (tid == 0) {
                while (*(volatile int*)&g_ctr[g] < NHIST) __nanosleep(128);
                s_ticket = atomicAdd(&g_adone[g], 1);
            }
            __syncthreads();
            __threadfence();
            // Last apply block past the spin (counter is final) resets group
            // state for the next graph replay.
            if (s_ticket == NAPPLY - 1 && tid == 0) {
                g_adone[g] = 0;
                g_ctr[g]   = 0;
            }

            // Build this channel's LUT locally (exact PIL integer math).
            const int hv = __ldcg(&g_hist[c * NB + tid]);
            H[tid]  = hv;
            CS[tid] = hv;
            __syncthreads();
#pragma unroll
            for (int off = 1; off < NB; off <<= 1) {       // inclusive scan
                int v = (tid >= off) ? CS[tid - off] : 0;
                __syncthreads();
                CS[tid] += v;
                __syncthreads();
            }
            RED[tid] = hv ? tid : -1;                      // last nonzero bin
            __syncthreads();
#pragma unroll
            for (int sdx = 128; sdx > 0; sdx >>= 1) {
                if (tid < sdx) RED[tid] = max(RED[tid], RED[tid + sdx]);
                __syncthreads();
            }
            const int last_val = H[RED[0]];
            const int step = (P - last_val) / 255;
            const int safe = step > 0 ? step : 1;
            const int prev = tid ? CS[tid - 1] : 0;
            int lv = (prev + step / 2) / safe;
            lv = min(max(lv, 0), 255);
            if (step == 0) lv = tid;       // passthrough as identity LUT
            LUT[tid] = (float)lv;
            __syncthreads();

            // This block is done reading g_hist[c]; the 16th (last) reader
            // zeroes the channel's histogram + ticket for the next replay.
            if (tid == 0) s_ticket = atomicAdd(&g_aread[c], 1);
            __syncthreads();
            if (s_ticket == APC - 1) {
                g_hist[c * NB + tid] = 0;
                if (tid == 0) g_aread[c] = 0;
            }

            // Apply this block's slice: 4096 float4, 2 loads in flight.
            const float4* bi =
                reinterpret_cast<const float4*>(in + (size_t)c * P) + j * (P / 4 / APC);
            float4* bo =
                reinterpret_cast<float4*>(out + (size_t)c * P) + j * (P / 4 / APC);
            for (int i = tid; i < P / 4 / APC; i += 512) {
                float4 x = bi[i];
                float4 y = bi[i + 256];
                float4 ox, oy;
                ox.x = LUT[(int)x.x]; ox.y = LUT[(int)x.y];
                ox.z = LUT[(int)x.z]; ox.w = LUT[(int)x.w];
                oy.x = LUT[(int)y.x]; oy.y = LUT[(int)y.y];
                oy.z = LUT[(int)y.z]; oy.w = LUT[(int)y.w];
                __stcs(&bo[i], ox);            // evict-first writes: protect L2
                __stcs(&bo[i + 256], oy);      // residency of upcoming input
            }
            __syncthreads();                    // smem reuse next group
        }
    }
}

// ---------------------------------------------------------------------------
extern "C" void kernel_launch(void* const* d_in, const int* in_sizes, int n_in,
                              void* d_out, int out_size) {
    const float* img = (const float*)d_in[0];
    float* out = (float*)d_out;
    fused_kernel<<<NBLK, 256>>>(img, out);
}